// round 1
// baseline (speedup 1.0000x reference)
#include <cuda_runtime.h>
#include <math.h>

// Problem constants
#define BATCH 4
#define T     4096
#define C     1024
#define H     64
#define TOTROWS (BATCH * T)          // 16384
#define SCALE 0.03125f               // C^-0.5 = 1/32

// Scratch for projected q, k, v (no cudaMalloc allowed)
__device__ float g_q[TOTROWS * H];
__device__ float g_k[TOTROWS * H];
__device__ float g_v[TOTROWS * H];

// ---------------------------------------------------------------------------
// Kernel A: QKV projection GEMM. out[m, n] = sum_k x[m, k] * W[k, n]
// M = 16384, K = 1024, N = 64. Tiles: BM=64, BN=64, BK=16, 256 threads,
// each thread computes a 4x4 micro-tile. grid.y selects which of Wq/Wk/Wv.
// ---------------------------------------------------------------------------
__global__ __launch_bounds__(256) void proj_kernel(
    const float* __restrict__ x,
    const float* __restrict__ Wq,
    const float* __restrict__ Wk,
    const float* __restrict__ Wv)
{
    const int which = blockIdx.y;
    const float* __restrict__ W = (which == 0) ? Wq : (which == 1) ? Wk : Wv;
    float* __restrict__ out = (which == 0) ? g_q : (which == 1) ? g_k : g_v;

    const int m0 = blockIdx.x * 64;
    const int tid = threadIdx.x;

    __shared__ float As[16][64];   // x tile, transposed: As[k][m]
    __shared__ float Bs[16][64];   // W tile: Bs[k][n]

    float acc[4][4] = {};

    const int lm = (tid >> 4) * 4;   // 0..60, row base within tile
    const int ln = (tid & 15) * 4;   // 0..60, col base within tile

    // Load mapping
    const int a_m  = tid >> 2;        // 0..63
    const int a_k  = (tid & 3) * 4;   // 0,4,8,12
    const int b_k  = tid >> 4;        // 0..15
    const int b_n  = (tid & 15) * 4;  // 0..60

    for (int k0 = 0; k0 < C; k0 += 16) {
        float4 xv = *(const float4*)(x + (size_t)(m0 + a_m) * C + k0 + a_k);
        As[a_k + 0][a_m] = xv.x;
        As[a_k + 1][a_m] = xv.y;
        As[a_k + 2][a_m] = xv.z;
        As[a_k + 3][a_m] = xv.w;

        *(float4*)&Bs[b_k][b_n] = *(const float4*)(W + (size_t)(k0 + b_k) * H + b_n);

        __syncthreads();

        #pragma unroll
        for (int kk = 0; kk < 16; kk++) {
            float a0 = As[kk][lm + 0];
            float a1 = As[kk][lm + 1];
            float a2 = As[kk][lm + 2];
            float a3 = As[kk][lm + 3];
            float4 b = *(const float4*)&Bs[kk][ln];
            acc[0][0] += a0 * b.x; acc[0][1] += a0 * b.y; acc[0][2] += a0 * b.z; acc[0][3] += a0 * b.w;
            acc[1][0] += a1 * b.x; acc[1][1] += a1 * b.y; acc[1][2] += a1 * b.z; acc[1][3] += a1 * b.w;
            acc[2][0] += a2 * b.x; acc[2][1] += a2 * b.y; acc[2][2] += a2 * b.z; acc[2][3] += a2 * b.w;
            acc[3][0] += a3 * b.x; acc[3][1] += a3 * b.y; acc[3][2] += a3 * b.z; acc[3][3] += a3 * b.w;
        }
        __syncthreads();
    }

    #pragma unroll
    for (int i = 0; i < 4; i++) {
        float4 v = make_float4(acc[i][0], acc[i][1], acc[i][2], acc[i][3]);
        *(float4*)(out + (size_t)(m0 + lm + i) * H + ln) = v;
    }
}

// ---------------------------------------------------------------------------
// Kernel B: causal flash attention, fp32, online softmax.
// 64 queries per block, 128 threads: 2 threads per query, each owning 32 of
// the 64 head dims. K/V tiles of 64 keys in shared memory, broadcast-read.
// Grid: BATCH * (T/64) = 256 blocks.
// ---------------------------------------------------------------------------
__global__ __launch_bounds__(128, 1) void attn_kernel(float* __restrict__ out)
{
    const int b    = blockIdx.x >> 6;       // T/64 = 64 q-blocks per batch
    const int qblk = blockIdx.x & 63;
    const int tid  = threadIdx.x;
    const int qi   = tid >> 1;              // 0..63 query within block
    const int half = tid & 1;               // which 32 head dims
    const int t    = qblk * 64 + qi;        // global query index

    __shared__ float Ks[64][64];
    __shared__ float Vs[64][64];

    const float* __restrict__ qp = g_q + ((size_t)b * T + t) * H + half * 32;
    float q[32];
    #pragma unroll
    for (int j4 = 0; j4 < 8; j4++) {
        float4 v = *(const float4*)(qp + j4 * 4);
        q[j4 * 4 + 0] = v.x; q[j4 * 4 + 1] = v.y;
        q[j4 * 4 + 2] = v.z; q[j4 * 4 + 3] = v.w;
    }

    float o[32];
    #pragma unroll
    for (int j = 0; j < 32; j++) o[j] = 0.f;
    float m = -1e30f;
    float l = 0.f;

    const float* __restrict__ kbase = g_k + (size_t)b * T * H;
    const float* __restrict__ vbase = g_v + (size_t)b * T * H;

    const int ntiles = qblk + 1;            // causal: keys up to qblk*64+63

    for (int tile = 0; tile < ntiles; tile++) {
        const int s0 = tile * 64;

        // Load 64x64 K and V tiles: 4096 floats each, 8 float4 per thread.
        #pragma unroll
        for (int j = 0; j < 8; j++) {
            int f   = j * 128 + tid;        // float4 index 0..1023
            int row = f >> 4;
            int col = (f & 15) * 4;
            *(float4*)&Ks[row][col] = *(const float4*)(kbase + (size_t)(s0 + row) * H + col);
            *(float4*)&Vs[row][col] = *(const float4*)(vbase + (size_t)(s0 + row) * H + col);
        }
        __syncthreads();

        for (int s = 0; s < 64; s++) {
            // Partial dot over this thread's 32 dims (broadcast shared reads)
            float x0 = 0.f, x1 = 0.f, x2 = 0.f, x3 = 0.f;
            const float* krow = &Ks[s][half * 32];
            #pragma unroll
            for (int j4 = 0; j4 < 8; j4++) {
                float4 kv = *(const float4*)(krow + j4 * 4);
                x0 += q[j4 * 4 + 0] * kv.x;
                x1 += q[j4 * 4 + 1] * kv.y;
                x2 += q[j4 * 4 + 2] * kv.z;
                x3 += q[j4 * 4 + 3] * kv.w;
            }
            float part = (x0 + x1) + (x2 + x3);
            // Pair-combine: both lanes of a pair compute bitwise-identical x.
            float x = part + __shfl_xor_sync(0xffffffffu, part, 1);
            x *= SCALE;

            if ((s0 + s) <= t) {            // causal mask (pair-converged)
                if (x > m) {
                    float corr = __expf(m - x);
                    l *= corr;
                    #pragma unroll
                    for (int j = 0; j < 32; j++) o[j] *= corr;
                    m = x;
                }
                float p = __expf(x - m);
                l += p;
                const float* vrow = &Vs[s][half * 32];
                #pragma unroll
                for (int j4 = 0; j4 < 8; j4++) {
                    float4 vv = *(const float4*)(vrow + j4 * 4);
                    o[j4 * 4 + 0] += p * vv.x;
                    o[j4 * 4 + 1] += p * vv.y;
                    o[j4 * 4 + 2] += p * vv.z;
                    o[j4 * 4 + 3] += p * vv.w;
                }
            }
        }
        __syncthreads();
    }

    const float inv_l = 1.0f / l;
    float* __restrict__ op = out + ((size_t)b * T + t) * H + half * 32;
    #pragma unroll
    for (int j4 = 0; j4 < 8; j4++) {
        float4 v = make_float4(o[j4 * 4 + 0] * inv_l, o[j4 * 4 + 1] * inv_l,
                               o[j4 * 4 + 2] * inv_l, o[j4 * 4 + 3] * inv_l);
        *(float4*)(op + j4 * 4) = v;
    }
}

// ---------------------------------------------------------------------------
extern "C" void kernel_launch(void* const* d_in, const int* in_sizes, int n_in,
                              void* d_out, int out_size)
{
    const float* x  = (const float*)d_in[0];
    const float* Wq = (const float*)d_in[1];
    const float* Wk = (const float*)d_in[2];
    const float* Wv = (const float*)d_in[3];
    float* out = (float*)d_out;

    dim3 pgrid(TOTROWS / 64, 3);
    proj_kernel<<<pgrid, 256>>>(x, Wq, Wk, Wv);

    attn_kernel<<<BATCH * (T / 64), 128>>>(out);
}

// round 2
// speedup vs baseline: 1.9105x; 1.9105x over previous
#include <cuda_runtime.h>
#include <math.h>

// Problem constants
#define BATCH 4
#define T     4096
#define C     1024
#define H     64
#define TOTROWS (BATCH * T)          // 16384
#define SCALE 0.03125f               // C^-0.5 = 1/32

// Scratch for projected q, k, v (no cudaMalloc allowed)
__device__ float g_q[TOTROWS * H];
__device__ float g_k[TOTROWS * H];
__device__ float g_v[TOTROWS * H];

// ---------------------------------------------------------------------------
// Kernel A: QKV projection GEMM. out[m, n] = sum_k x[m, k] * W[k, n]
// M = 16384, K = 1024, N = 64. Tiles: BM=64, BN=64, BK=16, 256 threads.
// ---------------------------------------------------------------------------
__global__ __launch_bounds__(256) void proj_kernel(
    const float* __restrict__ x,
    const float* __restrict__ Wq,
    const float* __restrict__ Wk,
    const float* __restrict__ Wv)
{
    const int which = blockIdx.y;
    const float* __restrict__ W = (which == 0) ? Wq : (which == 1) ? Wk : Wv;
    float* __restrict__ out = (which == 0) ? g_q : (which == 1) ? g_k : g_v;

    const int m0 = blockIdx.x * 64;
    const int tid = threadIdx.x;

    __shared__ float As[16][64];   // x tile, transposed: As[k][m]
    __shared__ float Bs[16][64];   // W tile: Bs[k][n]

    float acc[4][4] = {};

    const int lm = (tid >> 4) * 4;
    const int ln = (tid & 15) * 4;

    const int a_m  = tid >> 2;
    const int a_k  = (tid & 3) * 4;
    const int b_k  = tid >> 4;
    const int b_n  = (tid & 15) * 4;

    for (int k0 = 0; k0 < C; k0 += 16) {
        float4 xv = *(const float4*)(x + (size_t)(m0 + a_m) * C + k0 + a_k);
        As[a_k + 0][a_m] = xv.x;
        As[a_k + 1][a_m] = xv.y;
        As[a_k + 2][a_m] = xv.z;
        As[a_k + 3][a_m] = xv.w;

        *(float4*)&Bs[b_k][b_n] = *(const float4*)(W + (size_t)(k0 + b_k) * H + b_n);

        __syncthreads();

        #pragma unroll
        for (int kk = 0; kk < 16; kk++) {
            float a0 = As[kk][lm + 0];
            float a1 = As[kk][lm + 1];
            float a2 = As[kk][lm + 2];
            float a3 = As[kk][lm + 3];
            float4 b = *(const float4*)&Bs[kk][ln];
            acc[0][0] += a0 * b.x; acc[0][1] += a0 * b.y; acc[0][2] += a0 * b.z; acc[0][3] += a0 * b.w;
            acc[1][0] += a1 * b.x; acc[1][1] += a1 * b.y; acc[1][2] += a1 * b.z; acc[1][3] += a1 * b.w;
            acc[2][0] += a2 * b.x; acc[2][1] += a2 * b.y; acc[2][2] += a2 * b.z; acc[2][3] += a2 * b.w;
            acc[3][0] += a3 * b.x; acc[3][1] += a3 * b.y; acc[3][2] += a3 * b.z; acc[3][3] += a3 * b.w;
        }
        __syncthreads();
    }

    #pragma unroll
    for (int i = 0; i < 4; i++) {
        float4 v = make_float4(acc[i][0], acc[i][1], acc[i][2], acc[i][3]);
        *(float4*)(out + (size_t)(m0 + lm + i) * H + ln) = v;
    }
}

// ---------------------------------------------------------------------------
// Kernel B: register-tiled causal flash attention.
// Block = 128 threads (4 warps). Each block processes the q-tile PAIR
// (p, 127-p) of 32 queries each -> uniform work across blocks.
// Per key-tile of 64: S = Q*K^T as a register-tiled GEMM (4x4 per thread),
// online softmax with width-16 shuffle row reductions, P staged via
// warp-private smem, O += P*V as a second register-tiled GEMM.
// ---------------------------------------------------------------------------
#define QS_PAD 36
#define KS_PAD 68
#define PS_PAD 36
#define ATTN_SMEM_FLOATS (64*QS_PAD + 64*KS_PAD + 64*64 + 64*PS_PAD)

__global__ __launch_bounds__(128, 2) void attn_kernel(float* __restrict__ out)
{
    extern __shared__ float sm[];
    float* Qs = sm;                       // [64 h][QS_PAD]  (transposed, 32 q used)
    float* Ks = Qs + 64 * QS_PAD;         // [64 h][KS_PAD]  (transposed)
    float* Vs = Ks + 64 * KS_PAD;         // [64 s][64 h]
    float* Ps = Vs + 64 * 64;             // [64 s][PS_PAD]  (transposed, warp-private cols)

    const int b    = blockIdx.x >> 6;     // 64 pairs per batch
    const int pair = blockIdx.x & 63;
    const int tid  = threadIdx.x;
    const int w    = tid >> 5;
    const int lane = tid & 31;
    const int lq   = lane >> 4;           // 0..1: q row group
    const int ls   = lane & 15;           // 0..15: s/h col group
    const int qr   = w * 8 + lq * 4;      // local q row base (0..28)
    const int cb   = ls * 4;              // local s/h col base (0..60)

    const float* __restrict__ qg = g_q + (size_t)b * T * H;
    const float* __restrict__ kg = g_k + (size_t)b * T * H;
    const float* __restrict__ vg = g_v + (size_t)b * T * H;

    #pragma unroll
    for (int half = 0; half < 2; half++) {
        const int qt = (half == 0) ? pair : (127 - pair);  // q-tile index (32 rows)
        const int q0 = qt * 32;
        const int ntiles = (qt >> 1) + 1;                  // key tiles of 64

        // ---- load Q tile (32x64) transposed + pre-scaled ----
        __syncthreads();   // protect Qs/Ks/Vs from previous iteration readers
        #pragma unroll
        for (int j = 0; j < 4; j++) {
            int f   = j * 128 + tid;       // 512 float4 in tile
            int row = f >> 4;              // 0..31
            int c4  = (f & 15) * 4;
            float4 v = *(const float4*)(qg + (size_t)(q0 + row) * H + c4);
            Qs[(c4 + 0) * QS_PAD + row] = v.x * SCALE;
            Qs[(c4 + 1) * QS_PAD + row] = v.y * SCALE;
            Qs[(c4 + 2) * QS_PAD + row] = v.z * SCALE;
            Qs[(c4 + 3) * QS_PAD + row] = v.w * SCALE;
        }

        float O[4][4];
        #pragma unroll
        for (int i = 0; i < 4; i++)
            #pragma unroll
            for (int j = 0; j < 4; j++) O[i][j] = 0.f;
        float mrow[4], lrow[4];
        #pragma unroll
        for (int i = 0; i < 4; i++) { mrow[i] = -1e30f; lrow[i] = 0.f; }

        for (int tile = 0; tile < ntiles; tile++) {
            const int s0 = tile * 64;

            // ---- load K (transposed) and V (natural) tiles ----
            __syncthreads();
            #pragma unroll
            for (int j = 0; j < 8; j++) {
                int f   = j * 128 + tid;   // 1024 float4
                int row = f >> 4;          // 0..63
                int c4  = (f & 15) * 4;
                float4 kv = *(const float4*)(kg + (size_t)(s0 + row) * H + c4);
                Ks[(c4 + 0) * KS_PAD + row] = kv.x;
                Ks[(c4 + 1) * KS_PAD + row] = kv.y;
                Ks[(c4 + 2) * KS_PAD + row] = kv.z;
                Ks[(c4 + 3) * KS_PAD + row] = kv.w;
                float4 vv = *(const float4*)(vg + (size_t)(s0 + row) * H + c4);
                *(float4*)&Vs[row * 64 + c4] = vv;
            }
            __syncthreads();

            // ---- S = Q*K^T (4x4 per thread) ----
            float acc[4][4];
            #pragma unroll
            for (int i = 0; i < 4; i++)
                #pragma unroll
                for (int j = 0; j < 4; j++) acc[i][j] = 0.f;

            const float* qb = Qs + qr;
            const float* kb = Ks + cb;
            #pragma unroll 4
            for (int h = 0; h < 64; h++) {
                float4 qa = *(const float4*)(qb + h * QS_PAD);
                float4 ka = *(const float4*)(kb + h * KS_PAD);
                acc[0][0] += qa.x * ka.x; acc[0][1] += qa.x * ka.y; acc[0][2] += qa.x * ka.z; acc[0][3] += qa.x * ka.w;
                acc[1][0] += qa.y * ka.x; acc[1][1] += qa.y * ka.y; acc[1][2] += qa.y * ka.z; acc[1][3] += qa.y * ka.w;
                acc[2][0] += qa.z * ka.x; acc[2][1] += qa.z * ka.y; acc[2][2] += qa.z * ka.z; acc[2][3] += qa.z * ka.w;
                acc[3][0] += qa.w * ka.x; acc[3][1] += qa.w * ka.y; acc[3][2] += qa.w * ka.z; acc[3][3] += qa.w * ka.w;
            }

            // ---- causal mask on the diagonal tile (data, no divergence) ----
            if (tile == ntiles - 1) {
                #pragma unroll
                for (int i = 0; i < 4; i++) {
                    int qgl = q0 + qr + i;
                    #pragma unroll
                    for (int j = 0; j < 4; j++) {
                        int sgl = s0 + cb + j;
                        if (sgl > qgl) acc[i][j] = -1e30f;
                    }
                }
            }

            // ---- online softmax (rows shared by the 16 ls-lanes) ----
            #pragma unroll
            for (int i = 0; i < 4; i++) {
                float mx = fmaxf(fmaxf(acc[i][0], acc[i][1]), fmaxf(acc[i][2], acc[i][3]));
                #pragma unroll
                for (int d = 1; d < 16; d <<= 1)
                    mx = fmaxf(mx, __shfl_xor_sync(0xffffffffu, mx, d));
                float mn = fmaxf(mrow[i], mx);
                float corr = __expf(mrow[i] - mn);
                mrow[i] = mn;
                float rs = 0.f;
                #pragma unroll
                for (int j = 0; j < 4; j++) {
                    float p = __expf(acc[i][j] - mn);
                    acc[i][j] = p;
                    rs += p;
                }
                #pragma unroll
                for (int d = 1; d < 16; d <<= 1)
                    rs += __shfl_xor_sync(0xffffffffu, rs, d);
                lrow[i] = lrow[i] * corr + rs;
                #pragma unroll
                for (int j = 0; j < 4; j++) O[i][j] *= corr;
            }

            // ---- stage P (transposed, warp-private q-columns) ----
            __syncwarp();
            #pragma unroll
            for (int j = 0; j < 4; j++) {
                *(float4*)&Ps[(cb + j) * PS_PAD + qr] =
                    make_float4(acc[0][j], acc[1][j], acc[2][j], acc[3][j]);
            }
            __syncwarp();

            // ---- O += P*V (4x4 per thread) ----
            const float* pb = Ps + qr;
            const float* vb = Vs + cb;
            #pragma unroll 4
            for (int s = 0; s < 64; s++) {
                float4 pv = *(const float4*)(pb + s * PS_PAD);
                float4 vv = *(const float4*)(vb + s * 64);
                O[0][0] += pv.x * vv.x; O[0][1] += pv.x * vv.y; O[0][2] += pv.x * vv.z; O[0][3] += pv.x * vv.w;
                O[1][0] += pv.y * vv.x; O[1][1] += pv.y * vv.y; O[1][2] += pv.y * vv.z; O[1][3] += pv.y * vv.w;
                O[2][0] += pv.z * vv.x; O[2][1] += pv.z * vv.y; O[2][2] += pv.z * vv.z; O[2][3] += pv.z * vv.w;
                O[3][0] += pv.w * vv.x; O[3][1] += pv.w * vv.y; O[3][2] += pv.w * vv.z; O[3][3] += pv.w * vv.w;
            }
        }

        // ---- epilogue ----
        #pragma unroll
        for (int i = 0; i < 4; i++) {
            float inv = 1.0f / lrow[i];
            int qgl = q0 + qr + i;
            *(float4*)(out + ((size_t)b * T + qgl) * H + cb) =
                make_float4(O[i][0] * inv, O[i][1] * inv, O[i][2] * inv, O[i][3] * inv);
        }
    }
}

// ---------------------------------------------------------------------------
extern "C" void kernel_launch(void* const* d_in, const int* in_sizes, int n_in,
                              void* d_out, int out_size)
{
    const float* x  = (const float*)d_in[0];
    const float* Wq = (const float*)d_in[1];
    const float* Wk = (const float*)d_in[2];
    const float* Wv = (const float*)d_in[3];
    float* out = (float*)d_out;

    dim3 pgrid(TOTROWS / 64, 3);
    proj_kernel<<<pgrid, 256>>>(x, Wq, Wk, Wv);

    static int smem_set = 0;
    size_t smem_bytes = ATTN_SMEM_FLOATS * sizeof(float);
    if (!smem_set) {
        cudaFuncSetAttribute(attn_kernel,
                             cudaFuncAttributeMaxDynamicSharedMemorySize,
                             (int)smem_bytes);
        smem_set = 1;
    }
    attn_kernel<<<BATCH * 64, 128, smem_bytes>>>(out);
}

// round 7
// speedup vs baseline: 2.5165x; 1.3172x over previous
#include <cuda_runtime.h>
#include <math.h>
#include <stdint.h>

// Problem constants
#define BATCH 4
#define T     4096
#define C     1024
#define H     64
#define TOTROWS (BATCH * T)          // 16384
#define SCALE 0.03125f               // C^-0.5 = 1/32

// Scratch for projected q, k, v
__device__ float g_q[TOTROWS * H];
__device__ float g_k[TOTROWS * H];
__device__ float g_v[TOTROWS * H];

// ---------------------------------------------------------------------------
// tf32 helpers (warp-level mma.sync — compiles for compute_103, HMMA pipe)
// ---------------------------------------------------------------------------
__device__ __forceinline__ uint32_t f32_to_tf32(float x) {
    uint32_t y;
    asm("cvt.rna.tf32.f32 %0, %1;" : "=r"(y) : "f"(x));
    return y;
}

// D = A(16x8,row) * B(8x8,col) + D ; tf32 inputs, fp32 accum
__device__ __forceinline__ void mma_tf32(float c[4],
                                         uint32_t a0, uint32_t a1, uint32_t a2, uint32_t a3,
                                         uint32_t b0, uint32_t b1) {
    asm volatile(
        "mma.sync.aligned.m16n8k8.row.col.f32.tf32.tf32.f32 "
        "{%0,%1,%2,%3}, {%4,%5,%6,%7}, {%8,%9}, {%0,%1,%2,%3};"
        : "+f"(c[0]), "+f"(c[1]), "+f"(c[2]), "+f"(c[3])
        : "r"(a0), "r"(a1), "r"(a2), "r"(a3), "r"(b0), "r"(b1));
}

// ===========================================================================
// Kernel A: fused QKV projection with mma.sync tf32.
// 128 rows of x per CTA (256 threads = 8 warps, 16 rows/warp), N = 192 (q|k|v),
// K-chunks of 64. out[m, n'] = sum_k x[m,k] * W_{n'/64}[k, n'%64].
// ===========================================================================
#define XS_STR 68     // uint32 stride
#define WS_STR 200    // uint32 stride
#define PJ_SMEM_WORDS (128 * XS_STR + 64 * WS_STR)

__global__ __launch_bounds__(256, 1) void proj_mma_kernel(
    const float* __restrict__ x,
    const float* __restrict__ Wq,
    const float* __restrict__ Wk,
    const float* __restrict__ Wv)
{
    extern __shared__ uint32_t smw[];
    uint32_t* Xs = smw;                   // [128][XS_STR]
    uint32_t* Ws = smw + 128 * XS_STR;    // [64][WS_STR], cols 0..191 used

    const int tid  = threadIdx.x;
    const int wid  = tid >> 5;
    const int lane = tid & 31;
    const int r    = lane >> 2;           // 0..7
    const int cq   = lane & 3;            // 0..3
    const int w16  = wid * 16;
    const int m0   = blockIdx.x * 128;

    float acc[24][4];
    #pragma unroll
    for (int n = 0; n < 24; n++)
        #pragma unroll
        for (int j = 0; j < 4; j++) acc[n][j] = 0.f;

    for (int ch = 0; ch < 16; ch++) {
        const int k0 = ch * 64;
        __syncthreads();

        // x tile: 128 rows x 64 cols -> Xs (tf32)
        #pragma unroll
        for (int i = 0; i < 8; i++) {
            int f   = i * 256 + tid;            // 0..2047 float4
            int row = f >> 4;
            int c4  = (f & 15) * 4;
            float4 v = *(const float4*)(x + (size_t)(m0 + row) * C + k0 + c4);
            *(uint4*)&Xs[row * XS_STR + c4] = make_uint4(
                f32_to_tf32(v.x), f32_to_tf32(v.y), f32_to_tf32(v.z), f32_to_tf32(v.w));
        }
        // W tiles: 64 k x (3*64) n -> Ws (tf32)
        #pragma unroll
        for (int i = 0; i < 12; i++) {
            int f  = i * 256 + tid;             // 0..3071 float4
            int w  = f >> 10;                   // 0..2
            int rr = f & 1023;
            int kk = rr >> 4;                   // 0..63
            int n4 = (rr & 15) * 4;             // 0..60
            const float* Wp = (w == 0) ? Wq : (w == 1) ? Wk : Wv;
            float4 v = *(const float4*)(Wp + (size_t)(k0 + kk) * H + n4);
            *(uint4*)&Ws[kk * WS_STR + w * 64 + n4] = make_uint4(
                f32_to_tf32(v.x), f32_to_tf32(v.y), f32_to_tf32(v.z), f32_to_tf32(v.w));
        }
        __syncthreads();

        #pragma unroll
        for (int ks = 0; ks < 8; ks++) {
            uint32_t a0 = Xs[(w16 + r)     * XS_STR + ks * 8 + cq];
            uint32_t a1 = Xs[(w16 + r + 8) * XS_STR + ks * 8 + cq];
            uint32_t a2 = Xs[(w16 + r)     * XS_STR + ks * 8 + cq + 4];
            uint32_t a3 = Xs[(w16 + r + 8) * XS_STR + ks * 8 + cq + 4];
            #pragma unroll
            for (int n = 0; n < 24; n++) {
                uint32_t b0 = Ws[(ks * 8 + cq)     * WS_STR + n * 8 + r];
                uint32_t b1 = Ws[(ks * 8 + cq + 4) * WS_STR + n * 8 + r];
                mma_tf32(acc[n], a0, a1, a2, a3, b0, b1);
            }
        }
    }

    // epilogue
    const int tr0 = m0 + w16 + r;
    #pragma unroll
    for (int n = 0; n < 24; n++) {
        int which = n >> 3;
        int col   = (n * 8) & 63;
        float* op = (which == 0) ? g_q : (which == 1) ? g_k : g_v;
        *(float2*)(op + (size_t)tr0       * H + col + 2 * cq) = make_float2(acc[n][0], acc[n][1]);
        *(float2*)(op + (size_t)(tr0 + 8) * H + col + 2 * cq) = make_float2(acc[n][2], acc[n][3]);
    }
}

// ---------------------------------------------------------------------------
// Kernel B: register-tiled causal flash attention (round-2 version, verbatim;
// passed at rel_err 7.3e-7).
// ---------------------------------------------------------------------------
#define QS_PAD 36
#define KS_PAD 68
#define PS_PAD 36
#define ATTN_SMEM_FLOATS (64*QS_PAD + 64*KS_PAD + 64*64 + 64*PS_PAD)

__global__ __launch_bounds__(128, 2) void attn_kernel(float* __restrict__ out)
{
    extern __shared__ float sm[];
    float* Qs = sm;
    float* Ks = Qs + 64 * QS_PAD;
    float* Vs = Ks + 64 * KS_PAD;
    float* Ps = Vs + 64 * 64;

    const int b    = blockIdx.x >> 6;
    const int pair = blockIdx.x & 63;
    const int tid  = threadIdx.x;
    const int w    = tid >> 5;
    const int lane = tid & 31;
    const int lq   = lane >> 4;
    const int ls   = lane & 15;
    const int qr   = w * 8 + lq * 4;
    const int cb   = ls * 4;

    const float* __restrict__ qg = g_q + (size_t)b * T * H;
    const float* __restrict__ kg = g_k + (size_t)b * T * H;
    const float* __restrict__ vg = g_v + (size_t)b * T * H;

    #pragma unroll
    for (int half = 0; half < 2; half++) {
        const int qt = (half == 0) ? pair : (127 - pair);
        const int q0 = qt * 32;
        const int ntiles = (qt >> 1) + 1;

        __syncthreads();
        #pragma unroll
        for (int j = 0; j < 4; j++) {
            int f   = j * 128 + tid;
            int row = f >> 4;
            int c4  = (f & 15) * 4;
            float4 v = *(const float4*)(qg + (size_t)(q0 + row) * H + c4);
            Qs[(c4 + 0) * QS_PAD + row] = v.x * SCALE;
            Qs[(c4 + 1) * QS_PAD + row] = v.y * SCALE;
            Qs[(c4 + 2) * QS_PAD + row] = v.z * SCALE;
            Qs[(c4 + 3) * QS_PAD + row] = v.w * SCALE;
        }

        float O[4][4];
        #pragma unroll
        for (int i = 0; i < 4; i++)
            #pragma unroll
            for (int j = 0; j < 4; j++) O[i][j] = 0.f;
        float mrow[4], lrow[4];
        #pragma unroll
        for (int i = 0; i < 4; i++) { mrow[i] = -1e30f; lrow[i] = 0.f; }

        for (int tile = 0; tile < ntiles; tile++) {
            const int s0 = tile * 64;

            __syncthreads();
            #pragma unroll
            for (int j = 0; j < 8; j++) {
                int f   = j * 128 + tid;
                int row = f >> 4;
                int c4  = (f & 15) * 4;
                float4 kv = *(const float4*)(kg + (size_t)(s0 + row) * H + c4);
                Ks[(c4 + 0) * KS_PAD + row] = kv.x;
                Ks[(c4 + 1) * KS_PAD + row] = kv.y;
                Ks[(c4 + 2) * KS_PAD + row] = kv.z;
                Ks[(c4 + 3) * KS_PAD + row] = kv.w;
                float4 vv = *(const float4*)(vg + (size_t)(s0 + row) * H + c4);
                *(float4*)&Vs[row * 64 + c4] = vv;
            }
            __syncthreads();

            float acc[4][4];
            #pragma unroll
            for (int i = 0; i < 4; i++)
                #pragma unroll
                for (int j = 0; j < 4; j++) acc[i][j] = 0.f;

            const float* qb = Qs + qr;
            const float* kb = Ks + cb;
            #pragma unroll 4
            for (int h = 0; h < 64; h++) {
                float4 qa = *(const float4*)(qb + h * QS_PAD);
                float4 ka = *(const float4*)(kb + h * KS_PAD);
                acc[0][0] += qa.x * ka.x; acc[0][1] += qa.x * ka.y; acc[0][2] += qa.x * ka.z; acc[0][3] += qa.x * ka.w;
                acc[1][0] += qa.y * ka.x; acc[1][1] += qa.y * ka.y; acc[1][2] += qa.y * ka.z; acc[1][3] += qa.y * ka.w;
                acc[2][0] += qa.z * ka.x; acc[2][1] += qa.z * ka.y; acc[2][2] += qa.z * ka.z; acc[2][3] += qa.z * ka.w;
                acc[3][0] += qa.w * ka.x; acc[3][1] += qa.w * ka.y; acc[3][2] += qa.w * ka.z; acc[3][3] += qa.w * ka.w;
            }

            if (tile == ntiles - 1) {
                #pragma unroll
                for (int i = 0; i < 4; i++) {
                    int qgl = q0 + qr + i;
                    #pragma unroll
                    for (int j = 0; j < 4; j++) {
                        int sgl = s0 + cb + j;
                        if (sgl > qgl) acc[i][j] = -1e30f;
                    }
                }
            }

            #pragma unroll
            for (int i = 0; i < 4; i++) {
                float mx = fmaxf(fmaxf(acc[i][0], acc[i][1]), fmaxf(acc[i][2], acc[i][3]));
                #pragma unroll
                for (int d = 1; d < 16; d <<= 1)
                    mx = fmaxf(mx, __shfl_xor_sync(0xffffffffu, mx, d));
                float mn = fmaxf(mrow[i], mx);
                float corr = __expf(mrow[i] - mn);
                mrow[i] = mn;
                float rs = 0.f;
                #pragma unroll
                for (int j = 0; j < 4; j++) {
                    float p = __expf(acc[i][j] - mn);
                    acc[i][j] = p;
                    rs += p;
                }
                #pragma unroll
                for (int d = 1; d < 16; d <<= 1)
                    rs += __shfl_xor_sync(0xffffffffu, rs, d);
                lrow[i] = lrow[i] * corr + rs;
                #pragma unroll
                for (int j = 0; j < 4; j++) O[i][j] *= corr;
            }

            __syncwarp();
            #pragma unroll
            for (int j = 0; j < 4; j++) {
                *(float4*)&Ps[(cb + j) * PS_PAD + qr] =
                    make_float4(acc[0][j], acc[1][j], acc[2][j], acc[3][j]);
            }
            __syncwarp();

            const float* pb = Ps + qr;
            const float* vb = Vs + cb;
            #pragma unroll 4
            for (int s = 0; s < 64; s++) {
                float4 pv = *(const float4*)(pb + s * PS_PAD);
                float4 vv = *(const float4*)(vb + s * 64);
                O[0][0] += pv.x * vv.x; O[0][1] += pv.x * vv.y; O[0][2] += pv.x * vv.z; O[0][3] += pv.x * vv.w;
                O[1][0] += pv.y * vv.x; O[1][1] += pv.y * vv.y; O[1][2] += pv.y * vv.z; O[1][3] += pv.y * vv.w;
                O[2][0] += pv.z * vv.x; O[2][1] += pv.z * vv.y; O[2][2] += pv.z * vv.z; O[2][3] += pv.z * vv.w;
                O[3][0] += pv.w * vv.x; O[3][1] += pv.w * vv.y; O[3][2] += pv.w * vv.z; O[3][3] += pv.w * vv.w;
            }
        }

        #pragma unroll
        for (int i = 0; i < 4; i++) {
            float inv = 1.0f / lrow[i];
            int qgl = q0 + qr + i;
            *(float4*)(out + ((size_t)b * T + qgl) * H + cb) =
                make_float4(O[i][0] * inv, O[i][1] * inv, O[i][2] * inv, O[i][3] * inv);
        }
    }
}

// ---------------------------------------------------------------------------
extern "C" void kernel_launch(void* const* d_in, const int* in_sizes, int n_in,
                              void* d_out, int out_size)
{
    const float* x  = (const float*)d_in[0];
    const float* Wq = (const float*)d_in[1];
    const float* Wk = (const float*)d_in[2];
    const float* Wv = (const float*)d_in[3];
    float* out = (float*)d_out;

    static int attr_set = 0;
    const int pj_smem = PJ_SMEM_WORDS * 4;
    const size_t at_smem = ATTN_SMEM_FLOATS * sizeof(float);
    if (!attr_set) {
        cudaFuncSetAttribute(proj_mma_kernel,
                             cudaFuncAttributeMaxDynamicSharedMemorySize, pj_smem);
        cudaFuncSetAttribute(attn_kernel,
                             cudaFuncAttributeMaxDynamicSharedMemorySize, (int)at_smem);
        attr_set = 1;
    }

    proj_mma_kernel<<<TOTROWS / 128, 256, pj_smem>>>(x, Wq, Wk, Wv);
    attn_kernel<<<BATCH * 64, 128, at_smem>>>(out);
}

// round 8
// speedup vs baseline: 5.2345x; 2.0801x over previous
#include <cuda_runtime.h>
#include <math.h>
#include <stdint.h>

// Problem constants
#define BATCH 4
#define T     4096
#define C     1024
#define H     64
#define TOTROWS (BATCH * T)          // 16384
#define SCALE 0.03125f               // C^-0.5 = 1/32

// Scratch for projected q, k, v
__device__ float g_q[TOTROWS * H];
__device__ float g_k[TOTROWS * H];
__device__ float g_v[TOTROWS * H];

// ---------------------------------------------------------------------------
// tf32 helpers (warp-level mma.sync — compiles for compute_103, HMMA pipe)
// ---------------------------------------------------------------------------
__device__ __forceinline__ uint32_t f32_to_tf32(float x) {
    uint32_t y;
    asm("cvt.rna.tf32.f32 %0, %1;" : "=r"(y) : "f"(x));
    return y;
}

// D = A(16x8,row) * B(8x8,col) + D ; tf32 inputs, fp32 accum
__device__ __forceinline__ void mma_tf32(float c[4],
                                         uint32_t a0, uint32_t a1, uint32_t a2, uint32_t a3,
                                         uint32_t b0, uint32_t b1) {
    asm volatile(
        "mma.sync.aligned.m16n8k8.row.col.f32.tf32.tf32.f32 "
        "{%0,%1,%2,%3}, {%4,%5,%6,%7}, {%8,%9}, {%0,%1,%2,%3};"
        : "+f"(c[0]), "+f"(c[1]), "+f"(c[2]), "+f"(c[3])
        : "r"(a0), "r"(a1), "r"(a2), "r"(a3), "r"(b0), "r"(b1));
}

// ===========================================================================
// Kernel A: fused QKV projection with mma.sync tf32 (validated in round 7).
// ===========================================================================
#define XS_STR 68     // uint32 stride
#define WS_STR 200    // uint32 stride
#define PJ_SMEM_WORDS (128 * XS_STR + 64 * WS_STR)

__global__ __launch_bounds__(256, 1) void proj_mma_kernel(
    const float* __restrict__ x,
    const float* __restrict__ Wq,
    const float* __restrict__ Wk,
    const float* __restrict__ Wv)
{
    extern __shared__ uint32_t smw[];
    uint32_t* Xs = smw;                   // [128][XS_STR]
    uint32_t* Ws = smw + 128 * XS_STR;    // [64][WS_STR], cols 0..191 used

    const int tid  = threadIdx.x;
    const int wid  = tid >> 5;
    const int lane = tid & 31;
    const int r    = lane >> 2;           // 0..7
    const int cq   = lane & 3;            // 0..3
    const int w16  = wid * 16;
    const int m0   = blockIdx.x * 128;

    float acc[24][4];
    #pragma unroll
    for (int n = 0; n < 24; n++)
        #pragma unroll
        for (int j = 0; j < 4; j++) acc[n][j] = 0.f;

    for (int ch = 0; ch < 16; ch++) {
        const int k0 = ch * 64;
        __syncthreads();

        // x tile: 128 rows x 64 cols -> Xs (tf32)
        #pragma unroll
        for (int i = 0; i < 8; i++) {
            int f   = i * 256 + tid;            // 0..2047 float4
            int row = f >> 4;
            int c4  = (f & 15) * 4;
            float4 v = *(const float4*)(x + (size_t)(m0 + row) * C + k0 + c4);
            *(uint4*)&Xs[row * XS_STR + c4] = make_uint4(
                f32_to_tf32(v.x), f32_to_tf32(v.y), f32_to_tf32(v.z), f32_to_tf32(v.w));
        }
        // W tiles: 64 k x (3*64) n -> Ws (tf32)
        #pragma unroll
        for (int i = 0; i < 12; i++) {
            int f  = i * 256 + tid;             // 0..3071 float4
            int w  = f >> 10;                   // 0..2
            int rr = f & 1023;
            int kk = rr >> 4;                   // 0..63
            int n4 = (rr & 15) * 4;             // 0..60
            const float* Wp = (w == 0) ? Wq : (w == 1) ? Wk : Wv;
            float4 v = *(const float4*)(Wp + (size_t)(k0 + kk) * H + n4);
            *(uint4*)&Ws[kk * WS_STR + w * 64 + n4] = make_uint4(
                f32_to_tf32(v.x), f32_to_tf32(v.y), f32_to_tf32(v.z), f32_to_tf32(v.w));
        }
        __syncthreads();

        #pragma unroll
        for (int ks = 0; ks < 8; ks++) {
            uint32_t a0 = Xs[(w16 + r)     * XS_STR + ks * 8 + cq];
            uint32_t a1 = Xs[(w16 + r + 8) * XS_STR + ks * 8 + cq];
            uint32_t a2 = Xs[(w16 + r)     * XS_STR + ks * 8 + cq + 4];
            uint32_t a3 = Xs[(w16 + r + 8) * XS_STR + ks * 8 + cq + 4];
            #pragma unroll
            for (int n = 0; n < 24; n++) {
                uint32_t b0 = Ws[(ks * 8 + cq)     * WS_STR + n * 8 + r];
                uint32_t b1 = Ws[(ks * 8 + cq + 4) * WS_STR + n * 8 + r];
                mma_tf32(acc[n], a0, a1, a2, a3, b0, b1);
            }
        }
    }

    // epilogue
    const int tr0 = m0 + w16 + r;
    #pragma unroll
    for (int n = 0; n < 24; n++) {
        int which = n >> 3;
        int col   = (n * 8) & 63;
        float* op = (which == 0) ? g_q : (which == 1) ? g_k : g_v;
        *(float2*)(op + (size_t)tr0       * H + col + 2 * cq) = make_float2(acc[n][0], acc[n][1]);
        *(float2*)(op + (size_t)(tr0 + 8) * H + col + 2 * cq) = make_float2(acc[n][2], acc[n][3]);
    }
}

// ===========================================================================
// Kernel B: causal flash attention with mma.sync tf32 (FA2 style).
// 128 blocks (4 batches x 32 pairs), 128 threads = 4 warps, 16 q-rows/warp.
// q-tile pair (p, 63-p) of 64 rows -> 65 key-tiles per block, uniform.
// FIX vs round 4: Q-tile load covers all 64 rows (i < 8), not 32.
// ===========================================================================
#define QS_STR 68
#define KT_STR 72
#define VS_STR 72
#define PS_STR 68
#define AT_SMEM_WORDS (64*QS_STR + 64*KT_STR + 64*VS_STR + 4*16*PS_STR)

__global__ __launch_bounds__(128, 1) void attn_mma_kernel(float* __restrict__ out)
{
    extern __shared__ uint32_t sm[];
    uint32_t* Qs = sm;                          // [64][QS_STR] tf32 (scaled)
    uint32_t* Kt = Qs + 64 * QS_STR;            // [64 dim][KT_STR keys] tf32
    uint32_t* Vs = Kt + 64 * KT_STR;            // [64 s][VS_STR h] tf32
    uint32_t* Ps = Vs + 64 * VS_STR;            // per-warp [16][PS_STR] tf32

    const int b    = blockIdx.x >> 5;
    const int pair = blockIdx.x & 31;
    const int tid  = threadIdx.x;
    const int wid  = tid >> 5;
    const int lane = tid & 31;
    const int r    = lane >> 2;                 // 0..7
    const int cq   = lane & 3;                  // 0..3
    const int w16  = wid * 16;
    uint32_t* Pw   = Ps + wid * 16 * PS_STR;

    const float* __restrict__ qg = g_q + (size_t)b * T * H;
    const float* __restrict__ kg = g_k + (size_t)b * T * H;
    const float* __restrict__ vg = g_v + (size_t)b * T * H;

    #pragma unroll 1
    for (int half = 0; half < 2; half++) {
        const int qt = (half == 0) ? pair : (63 - pair);
        const int q0 = qt * 64;
        const int ntiles = qt + 1;

        __syncthreads();
        // load Q tile: 64 rows x 64 cols = 1024 float4 (scaled, tf32)
        #pragma unroll
        for (int i = 0; i < 8; i++) {
            int f   = i * 128 + tid;            // 0..1023 float4
            int row = f >> 4;                   // 0..63
            int c4  = (f & 15) * 4;
            float4 v = *(const float4*)(qg + (size_t)(q0 + row) * H + c4);
            *(uint4*)&Qs[row * QS_STR + c4] = make_uint4(
                f32_to_tf32(v.x * SCALE), f32_to_tf32(v.y * SCALE),
                f32_to_tf32(v.z * SCALE), f32_to_tf32(v.w * SCALE));
        }
        __syncthreads();

        // Q A-fragments: persistent in registers
        uint32_t qa[8][4];
        #pragma unroll
        for (int ks = 0; ks < 8; ks++) {
            qa[ks][0] = Qs[(w16 + r)     * QS_STR + ks * 8 + cq];
            qa[ks][1] = Qs[(w16 + r + 8) * QS_STR + ks * 8 + cq];
            qa[ks][2] = Qs[(w16 + r)     * QS_STR + ks * 8 + cq + 4];
            qa[ks][3] = Qs[(w16 + r + 8) * QS_STR + ks * 8 + cq + 4];
        }

        float O[8][4];
        #pragma unroll
        for (int n = 0; n < 8; n++)
            #pragma unroll
            for (int j = 0; j < 4; j++) O[n][j] = 0.f;
        float m0h = -1e30f, m1h = -1e30f, l0 = 0.f, l1 = 0.f;

        const int tr0g = q0 + w16 + r;
        const int tr1g = tr0g + 8;

        for (int tile = 0; tile < ntiles; tile++) {
            const int s0 = tile * 64;

            __syncthreads();   // everyone done reading Kt/Vs of previous tile
            #pragma unroll
            for (int i = 0; i < 8; i++) {
                int f   = i * 128 + tid;        // 1024 float4
                int row = f >> 4;               // key index 0..63
                int c4  = (f & 15) * 4;         // dim base
                float4 kv = *(const float4*)(kg + (size_t)(s0 + row) * H + c4);
                Kt[(c4 + 0) * KT_STR + row] = f32_to_tf32(kv.x);
                Kt[(c4 + 1) * KT_STR + row] = f32_to_tf32(kv.y);
                Kt[(c4 + 2) * KT_STR + row] = f32_to_tf32(kv.z);
                Kt[(c4 + 3) * KT_STR + row] = f32_to_tf32(kv.w);
                float4 vv = *(const float4*)(vg + (size_t)(s0 + row) * H + c4);
                *(uint4*)&Vs[row * VS_STR + c4] = make_uint4(
                    f32_to_tf32(vv.x), f32_to_tf32(vv.y),
                    f32_to_tf32(vv.z), f32_to_tf32(vv.w));
            }
            __syncthreads();

            // ---- S = Q * K^T ----
            float S[8][4];
            #pragma unroll
            for (int n = 0; n < 8; n++) {
                #pragma unroll
                for (int j = 0; j < 4; j++) S[n][j] = 0.f;
            }
            #pragma unroll
            for (int ks = 0; ks < 8; ks++) {
                #pragma unroll
                for (int n = 0; n < 8; n++) {
                    uint32_t b0 = Kt[(ks * 8 + cq)     * KT_STR + n * 8 + r];
                    uint32_t b1 = Kt[(ks * 8 + cq + 4) * KT_STR + n * 8 + r];
                    mma_tf32(S[n], qa[ks][0], qa[ks][1], qa[ks][2], qa[ks][3], b0, b1);
                }
            }

            // ---- causal mask on diagonal tile ----
            if (tile == qt) {
                #pragma unroll
                for (int n = 0; n < 8; n++) {
                    int col0 = s0 + n * 8 + 2 * cq;
                    int col1 = col0 + 1;
                    if (col0 > tr0g) S[n][0] = -1e30f;
                    if (col1 > tr0g) S[n][1] = -1e30f;
                    if (col0 > tr1g) S[n][2] = -1e30f;
                    if (col1 > tr1g) S[n][3] = -1e30f;
                }
            }

            // ---- online softmax (rows split: [0,1] row r; [2,3] row r+8) ----
            float mx0 = -1e30f, mx1 = -1e30f;
            #pragma unroll
            for (int n = 0; n < 8; n++) {
                mx0 = fmaxf(mx0, fmaxf(S[n][0], S[n][1]));
                mx1 = fmaxf(mx1, fmaxf(S[n][2], S[n][3]));
            }
            mx0 = fmaxf(mx0, __shfl_xor_sync(0xffffffffu, mx0, 1));
            mx0 = fmaxf(mx0, __shfl_xor_sync(0xffffffffu, mx0, 2));
            mx1 = fmaxf(mx1, __shfl_xor_sync(0xffffffffu, mx1, 1));
            mx1 = fmaxf(mx1, __shfl_xor_sync(0xffffffffu, mx1, 2));

            float mn0 = fmaxf(m0h, mx0);
            float mn1 = fmaxf(m1h, mx1);
            float corr0 = __expf(m0h - mn0);
            float corr1 = __expf(m1h - mn1);
            m0h = mn0; m1h = mn1;

            float rs0 = 0.f, rs1 = 0.f;
            #pragma unroll
            for (int n = 0; n < 8; n++) {
                uint32_t p00 = f32_to_tf32(__expf(S[n][0] - mn0));
                uint32_t p01 = f32_to_tf32(__expf(S[n][1] - mn0));
                uint32_t p10 = f32_to_tf32(__expf(S[n][2] - mn1));
                uint32_t p11 = f32_to_tf32(__expf(S[n][3] - mn1));
                rs0 += __uint_as_float(p00) + __uint_as_float(p01);
                rs1 += __uint_as_float(p10) + __uint_as_float(p11);
                *(uint2*)&Pw[r       * PS_STR + n * 8 + 2 * cq] = make_uint2(p00, p01);
                *(uint2*)&Pw[(r + 8) * PS_STR + n * 8 + 2 * cq] = make_uint2(p10, p11);
            }
            rs0 += __shfl_xor_sync(0xffffffffu, rs0, 1);
            rs0 += __shfl_xor_sync(0xffffffffu, rs0, 2);
            rs1 += __shfl_xor_sync(0xffffffffu, rs1, 1);
            rs1 += __shfl_xor_sync(0xffffffffu, rs1, 2);
            l0 = l0 * corr0 + rs0;
            l1 = l1 * corr1 + rs1;

            #pragma unroll
            for (int n = 0; n < 8; n++) {
                O[n][0] *= corr0; O[n][1] *= corr0;
                O[n][2] *= corr1; O[n][3] *= corr1;
            }
            __syncwarp();

            // ---- O += P * V ----
            #pragma unroll
            for (int ks = 0; ks < 8; ks++) {
                uint32_t a0 = Pw[r       * PS_STR + ks * 8 + cq];
                uint32_t a1 = Pw[(r + 8) * PS_STR + ks * 8 + cq];
                uint32_t a2 = Pw[r       * PS_STR + ks * 8 + cq + 4];
                uint32_t a3 = Pw[(r + 8) * PS_STR + ks * 8 + cq + 4];
                #pragma unroll
                for (int n = 0; n < 8; n++) {
                    uint32_t b0 = Vs[(ks * 8 + cq)     * VS_STR + n * 8 + r];
                    uint32_t b1 = Vs[(ks * 8 + cq + 4) * VS_STR + n * 8 + r];
                    mma_tf32(O[n], a0, a1, a2, a3, b0, b1);
                }
            }
            __syncwarp();
        }

        // ---- epilogue ----
        float inv0 = 1.0f / l0;
        float inv1 = 1.0f / l1;
        float* o0 = out + ((size_t)b * T + tr0g) * H;
        float* o1 = out + ((size_t)b * T + tr1g) * H;
        #pragma unroll
        for (int n = 0; n < 8; n++) {
            *(float2*)(o0 + n * 8 + 2 * cq) = make_float2(O[n][0] * inv0, O[n][1] * inv0);
            *(float2*)(o1 + n * 8 + 2 * cq) = make_float2(O[n][2] * inv1, O[n][3] * inv1);
        }
    }
}

// ---------------------------------------------------------------------------
extern "C" void kernel_launch(void* const* d_in, const int* in_sizes, int n_in,
                              void* d_out, int out_size)
{
    const float* x  = (const float*)d_in[0];
    const float* Wq = (const float*)d_in[1];
    const float* Wk = (const float*)d_in[2];
    const float* Wv = (const float*)d_in[3];
    float* out = (float*)d_out;

    static int attr_set = 0;
    const int pj_smem = PJ_SMEM_WORDS * 4;
    const int at_smem = AT_SMEM_WORDS * 4;
    if (!attr_set) {
        cudaFuncSetAttribute(proj_mma_kernel,
                             cudaFuncAttributeMaxDynamicSharedMemorySize, pj_smem);
        cudaFuncSetAttribute(attn_mma_kernel,
                             cudaFuncAttributeMaxDynamicSharedMemorySize, at_smem);
        attr_set = 1;
    }

    proj_mma_kernel<<<TOTROWS / 128, 256, pj_smem>>>(x, Wq, Wk, Wv);
    attn_mma_kernel<<<BATCH * 32, 128, at_smem>>>(out);
}